// round 9
// baseline (speedup 1.0000x reference)
#include <cuda_runtime.h>
#include <cstddef>

// Fixed shapes
#define T_STEPS 336
#define NT      256          // 8 warps, 2 per SMSP
#define NCTAS   128          // 8 batch elems per CTA

typedef unsigned long long u64;

// ---- shared memory layout (float offsets) ----
// Weight segment layout (per K-segment, PQ = K/8 pairs per k-quarter):
//   block (kq, pq) of 512 floats:
//     [0..255]  if-plane: j*4 + {Wi_k, Wi_k1, Wf_k, Wf_k1}
//     [256..511] go-plane: j*4 + {Wg_k, Wg_k1, Wo_k, Wo_k1}
//   block offset = (kq*PQ + pq)*512
#define OFF_W0X 0            // K=16, PQ=2  -> 4096 floats
#define OFF_W0H 4096         // K=64, PQ=8  -> 16384
#define OFF_W1X 20480        // K=64 -> 16384
#define OFF_W1H 36864        // K=64 -> 16384
#define OFF_B   53248        // 512: [layer*256 + gate*64 + j]
#define OFF_X   53760        // 2 bufs x (8 elems x 16)
#define OFF_H0  54016        // 2 bufs x (8 elems x 64)
#define OFF_H1  55040        // 2 bufs x 512
#define SMEM_FLOATS 56064
#define SMEM_BYTES (SMEM_FLOATS * 4)   // 224,256 B < 232,448 cap

// ---- packed helpers ----
__device__ __forceinline__ u64 fma2(u64 a, u64 b, u64 c) {
    u64 d;
    asm("fma.rn.f32x2 %0, %1, %2, %3;" : "=l"(d) : "l"(a), "l"(b), "l"(c));
    return d;
}
__device__ __forceinline__ ulonglong2 lds2(const float* p) {
    return *reinterpret_cast<const ulonglong2*>(p);
}
__device__ __forceinline__ float foldadd(u64 v) {
    float lo, hi;
    asm("mov.b64 {%0,%1}, %2;" : "=f"(lo), "=f"(hi) : "l"(v));
    return lo + hi;
}
__device__ __forceinline__ float sigf(float x) {
    return __fdividef(1.0f, 1.0f + __expf(-x));
}
__device__ __forceinline__ float tanhe(float x) {
    return 1.0f - __fdividef(2.0f, __expf(2.0f * x) + 1.0f);
}

// GEMM over NCH chunks (chunk = 2 k-pairs = 4 k of this lane's k-quarter).
// acc[gate*8 + e]. wbase: seg + (kq*PQ)*512 + j*4 baked. hbase: buf + kq-offset baked.
template<int NCH, int HS>
__device__ __forceinline__ void gemm8(u64* __restrict__ acc,
                                      const float* __restrict__ wbase,
                                      const float* __restrict__ hbase)
{
#pragma unroll
    for (int c = 0; c < NCH; ++c) {
        ulonglong2 hv[8];
#pragma unroll
        for (int e = 0; e < 8; ++e) hv[e] = lds2(hbase + e * HS + c * 4);
#pragma unroll
        for (int ki2 = 0; ki2 < 2; ++ki2) {
            const float* wr = wbase + (size_t)(c * 2 + ki2) * 512;
            const ulonglong2 wif = lds2(wr);        // (Wi pair),(Wf pair)
            const ulonglong2 wgo = lds2(wr + 256);  // (Wg pair),(Wo pair)
#pragma unroll
            for (int e = 0; e < 8; ++e) {
                const u64 h = ki2 ? hv[e].y : hv[e].x;
                acc[e]      = fma2(wif.x, h, acc[e]);
                acc[8 + e]  = fma2(wif.y, h, acc[8 + e]);
                acc[16 + e] = fma2(wgo.x, h, acc[16 + e]);
                acc[24 + e] = fma2(wgo.y, h, acc[24 + e]);
            }
        }
    }
}

__global__ void __launch_bounds__(NT, 1)
lstm2_kernel(const float* __restrict__ x,
             const float* __restrict__ Wih0, const float* __restrict__ Whh0,
             const float* __restrict__ bih0, const float* __restrict__ bhh0,
             const float* __restrict__ Wih1, const float* __restrict__ Whh1,
             const float* __restrict__ bih1, const float* __restrict__ bhh1,
             const float* __restrict__ Wfc,  const float* __restrict__ bfc,
             float* __restrict__ out)
{
    extern __shared__ float sh[];
    const int tid = threadIdx.x;

    // ---- stage weights ----
    // W_ih0: [256 x 16], PQ=2
    for (int idx = tid; idx < 256 * 16; idx += NT) {
        const int gr = idx >> 4, k = idx & 15;
        const int gate = gr >> 6, j = gr & 63;
        const int p2 = k >> 1, kq = p2 >> 1, pq = p2 & 1;
        sh[OFF_W0X + (kq * 2 + pq) * 512 + (gate >> 1) * 256 + j * 4
           + (gate & 1) * 2 + (k & 1)] = Wih0[idx];
    }
    // K=64 segments, PQ=8
    for (int idx = tid; idx < 256 * 64; idx += NT) {
        const int gr = idx >> 6, k = idx & 63;
        const int gate = gr >> 6, j = gr & 63;
        const int p2 = k >> 1, kq = p2 >> 3, pq = p2 & 7;
        const int o = (kq * 8 + pq) * 512 + (gate >> 1) * 256 + j * 4
                      + (gate & 1) * 2 + (k & 1);
        sh[OFF_W0H + o] = Whh0[idx];
        sh[OFF_W1X + o] = Wih1[idx];
        sh[OFF_W1H + o] = Whh1[idx];
    }
    // combined biases: [layer][gate*64 + j]
    {
        sh[OFF_B + tid]       = bih0[tid] + bhh0[tid];
        sh[OFF_B + 256 + tid] = bih1[tid] + bhh1[tid];
    }
    // zero h buffers (h0 + h1, both bufs: 2048 floats)
    for (int idx = tid; idx < 2048; idx += NT) sh[OFF_H0 + idx] = 0.0f;

    // ---- thread mapping: warp = j-octant; lane = kq*8 + j8 ----
    const int wid = tid >> 5, lane = tid & 31;
    const int j8  = lane & 7;
    const int kq  = lane >> 3;           // k-quarter 0..3
    const int j   = wid * 8 + j8;
    const int jo4 = j * 4;

    // x staging: kq==1 octet; (elem = wid, k-pair = j8)
    const float* xptr = x + (size_t)(blockIdx.x * 8 + wid) * T_STEPS * 16 + j8 * 2;
    float2 xv = make_float2(0.f, 0.f);
    if (kq == 1) {
        const float2 x0 = *reinterpret_cast<const float2*>(xptr);
        *reinterpret_cast<float2*>(&sh[OFF_X + wid * 16 + j8 * 2]) = x0;   // buf 0
        xv = *reinterpret_cast<const float2*>(xptr + 16);                  // x(1)
    }
    __syncthreads();

    // biases for this lane's j
    const float b0i = sh[OFF_B +   0 + j], b0f = sh[OFF_B +  64 + j];
    const float b0g = sh[OFF_B + 128 + j], b0o = sh[OFF_B + 192 + j];
    const float b1i = sh[OFF_B + 256 + j], b1f = sh[OFF_B + 320 + j];
    const float b1g = sh[OFF_B + 384 + j], b1o = sh[OFF_B + 448 + j];

    // lane-baked weight bases
    const float* w0x = &sh[OFF_W0X + (kq * 2) * 512 + jo4];
    const float* w0h = &sh[OFF_W0H + (kq * 8) * 512 + jo4];
    const float* w1x = &sh[OFF_W1X + (kq * 8) * 512 + jo4];
    const float* w1h = &sh[OFF_W1H + (kq * 8) * 512 + jo4];

    const bool act = !(kq & 1);          // kq 0 and 2 do activations
    const int  eb  = (kq & 2) * 2;       // kq0 -> elems 0-3, kq2 -> elems 4-7
    float c0[4] = {0.f, 0.f, 0.f, 0.f};
    float c1[4] = {0.f, 0.f, 0.f, 0.f};

    int p = 0;
    for (int t = 0; t < T_STEPS; ++t) {
        __syncthreads();   // BAR A: x(t), h0(t-1), h1(t-1) visible

        // ================= Layer 0 =================
        u64 acc[32];
#pragma unroll
        for (int i = 0; i < 32; ++i) acc[i] = 0ull;
        gemm8<1, 16>(acc, w0x, &sh[OFF_X + p * 128 + kq * 4]);
        gemm8<4, 64>(acc, w0h, &sh[OFF_H0 + p * 512 + kq * 16]);

        float s[32];
#pragma unroll
        for (int i = 0; i < 32; ++i) s[i] = foldadd(acc[i]);
#pragma unroll
        for (int i = 0; i < 32; ++i) s[i] += __shfl_xor_sync(0xffffffffu, s[i], 8);
#pragma unroll
        for (int i = 0; i < 32; ++i) s[i] += __shfl_xor_sync(0xffffffffu, s[i], 16);

        if (act) {
            float* hw = &sh[OFF_H0 + (1 - p) * 512 + j];
#pragma unroll
            for (int q = 0; q < 4; ++q) {
                const int e = eb + q;
                const float gi = sigf(s[e] + b0i);
                const float gf = sigf(s[8 + e] + b0f);
                const float gg = tanhe(s[16 + e] + b0g);
                const float go = sigf(s[24 + e] + b0o);
                c0[q] = fmaf(gf, c0[q], gi * gg);
                hw[e * 64] = go * tanhe(c0[q]);
            }
        } else if (kq == 1) {
            if (t + 1 < T_STEPS)
                *reinterpret_cast<float2*>(&sh[OFF_X + (1 - p) * 128 + wid * 16 + j8 * 2]) = xv;
            if (t + 2 < T_STEPS)
                xv = *reinterpret_cast<const float2*>(xptr + (size_t)(t + 2) * 16);
        }
        __syncthreads();   // BAR B: h0(t), x(t+1) visible

        // ================= Layer 1 =================
#pragma unroll
        for (int i = 0; i < 32; ++i) acc[i] = 0ull;
        gemm8<4, 64>(acc, w1x, &sh[OFF_H0 + (1 - p) * 512 + kq * 16]);
        gemm8<4, 64>(acc, w1h, &sh[OFF_H1 + p * 512 + kq * 16]);

#pragma unroll
        for (int i = 0; i < 32; ++i) s[i] = foldadd(acc[i]);
#pragma unroll
        for (int i = 0; i < 32; ++i) s[i] += __shfl_xor_sync(0xffffffffu, s[i], 8);
#pragma unroll
        for (int i = 0; i < 32; ++i) s[i] += __shfl_xor_sync(0xffffffffu, s[i], 16);

        if (act) {
            float* hw = &sh[OFF_H1 + (1 - p) * 512 + j];
#pragma unroll
            for (int q = 0; q < 4; ++q) {
                const int e = eb + q;
                const float gi = sigf(s[e] + b1i);
                const float gf = sigf(s[8 + e] + b1f);
                const float gg = tanhe(s[16 + e] + b1g);
                const float go = sigf(s[24 + e] + b1o);
                c1[q] = fmaf(gf, c1[q], gi * gg);
                hw[e * 64] = go * tanhe(c1[q]);
            }
        }
        p ^= 1;
    }

    __syncthreads();

    // ---- FC head: out[b] = dot(Wfc, h1_last[b]) + bfc ----
    if (tid < 8) {
        const float* hv = &sh[OFF_H1 + p * 512 + tid * 64];
        float sum = 0.0f;
#pragma unroll 8
        for (int k = 0; k < 64; ++k) sum += Wfc[k] * hv[k];
        out[blockIdx.x * 8 + tid] = sum + bfc[0];
    }
}

extern "C" void kernel_launch(void* const* d_in, const int* in_sizes, int n_in,
                              void* d_out, int out_size)
{
    const float* x    = (const float*)d_in[0];
    const float* Wih0 = (const float*)d_in[1];
    const float* Whh0 = (const float*)d_in[2];
    const float* bih0 = (const float*)d_in[3];
    const float* bhh0 = (const float*)d_in[4];
    const float* Wih1 = (const float*)d_in[5];
    const float* Whh1 = (const float*)d_in[6];
    const float* bih1 = (const float*)d_in[7];
    const float* bhh1 = (const float*)d_in[8];
    const float* Wfc  = (const float*)d_in[9];
    const float* bfc  = (const float*)d_in[10];
    float* out = (float*)d_out;

    cudaFuncSetAttribute(lstm2_kernel,
                         cudaFuncAttributeMaxDynamicSharedMemorySize, SMEM_BYTES);
    lstm2_kernel<<<NCTAS, NT, SMEM_BYTES>>>(
        x, Wih0, Whh0, bih0, bhh0, Wih1, Whh1, bih1, bhh1, Wfc, bfc, out);
}